// round 11
// baseline (speedup 1.0000x reference)
#include <cuda_runtime.h>
#include <cuda_bf16.h>
#include <math.h>
#include <stdint.h>

// Problem constants (fixed instance)
constexpr int NP   = 1024;   // N == N_ (train/test points)
constexpr int LT   = 4;      // tasks
constexpr int RNK_MAX = 8;
constexpr int NTOT = 1152;   // RHS width: 1024 Cx cols + 1 ytilde col + pad to 9*128
constexpr int NKB  = 16;     // 1024 / 64 block steps

// Output offsets (fp32 elements)
constexpr size_t OFF_FMEAN = 0;
constexpr size_t OFF_FVAR  = 4096;
constexpr size_t OFF_NOISE = OFF_FVAR + (size_t)4096 * 4096;
constexpr size_t OFF_OUT4  = OFF_NOISE + (size_t)4096 * 4096;

// -------- device scratch (static, no allocation) --------
__device__ float g_A[LT * NP * NP];          // lambda_c*C + I, then Cholesky L (lower)
__device__ float g_B[LT * NP * NTOT];        // RHS -> forward-solved P_c (and w_c in col 1024)
__device__ float g_H[LT * NP * NTOT];        // H_c = P_c^T * P_c  (col 1024 = g_c)
__device__ float g_Cxx[NP * NP];             // rbf(test_X, test_X)
__device__ float g_Linv[LT * NKB * 64 * 64]; // per-step 64x64 diag-block inverses
__device__ __nv_bfloat16 g_Qh[LT * (size_t)NTOT * NP]; // Q = P^T, bf16 hi
__device__ __nv_bfloat16 g_Ql[LT * (size_t)NTOT * NP]; // Q residual, bf16 lo
__device__ float g_lambda[LT];
__device__ float g_R[LT * LT];               // R = U^T Dn^{-1/2}
__device__ float g_M[LT * LT];               // M = R * T
__device__ float g_Tm[LT * LT];              // task_K
__device__ float g_noise[LT];                // exp(log_noise)

// -------- packed fp32x2 helpers --------
__device__ __forceinline__ unsigned long long f2pack(float lo, float hi)
{
    unsigned long long r;
    asm("mov.b64 %0, {%1, %2};" : "=l"(r) : "f"(lo), "f"(hi));
    return r;
}
__device__ __forceinline__ void f2unpack(unsigned long long v, float& lo, float& hi)
{
    asm("mov.b64 {%0, %1}, %2;" : "=f"(lo), "=f"(hi) : "l"(v));
}
__device__ __forceinline__ void f2fma(unsigned long long& d,
                                      unsigned long long a, unsigned long long b)
{
    asm("fma.rn.f32x2 %0, %1, %2, %3;" : "=l"(d) : "l"(a), "l"(b), "l"(d));
}

// -------- mma.sync / ldmatrix helpers (arch-portable tensor path) --------
__device__ __forceinline__ uint32_t smem_u32(const void* p)
{
    uint32_t a;
    asm("{ .reg .u64 t; cvta.to.shared.u64 t, %1; cvt.u32.u64 %0, t; }" : "=r"(a) : "l"(p));
    return a;
}
__device__ __forceinline__ void ldmx4(uint32_t* r, uint32_t addr)
{
    asm volatile("ldmatrix.sync.aligned.m8n8.x4.shared.b16 {%0,%1,%2,%3}, [%4];"
        : "=r"(r[0]), "=r"(r[1]), "=r"(r[2]), "=r"(r[3]) : "r"(addr));
}
__device__ __forceinline__ void mma16816(float* d, const uint32_t* a,
                                         uint32_t b0, uint32_t b1)
{
    asm volatile(
        "mma.sync.aligned.m16n8k16.row.col.f32.bf16.bf16.f32 "
        "{%0,%1,%2,%3}, {%4,%5,%6,%7}, {%8,%9}, {%0,%1,%2,%3};"
        : "+f"(d[0]), "+f"(d[1]), "+f"(d[2]), "+f"(d[3])
        : "r"(a[0]), "r"(a[1]), "r"(a[2]), "r"(a[3]), "r"(b0), "r"(b1));
}
__device__ __forceinline__ void bfsplit(float v, __nv_bfloat16& h, __nv_bfloat16& l)
{
    h = __float2bfloat16(v);
    l = __float2bfloat16(v - __bfloat162float(h));
}

// =====================================================================
// Small setup: task_K, 4x4 Jacobi eigendecomposition, R, M (fp32, 10 sweeps)
// =====================================================================
__global__ void k_setup(const float* __restrict__ cf,
                        const float* __restrict__ log_var,
                        const float* __restrict__ log_noise,
                        int rank)
{
    if (threadIdx.x != 0) return;
    float T[LT][LT], Tt[LT][LT], U[LT][LT], sv[LT];
#pragma unroll
    for (int a = 0; a < LT; a++) sv[a] = expf(-0.5f * log_noise[a]);
    for (int a = 0; a < LT; a++)
        for (int b = 0; b < LT; b++) {
            float s = 0.0f;
            for (int r = 0; r < rank && r < RNK_MAX; r++)
                s += cf[a * rank + r] * cf[b * rank + r];
            if (a == b) s += expf(log_var[a]);
            T[a][b] = s;
        }
#pragma unroll
    for (int a = 0; a < LT; a++)
#pragma unroll
        for (int b = 0; b < LT; b++) {
            Tt[a][b] = sv[a] * sv[b] * T[a][b];
            U[a][b] = (a == b) ? 1.0f : 0.0f;
        }
#pragma unroll 1
    for (int sweep = 0; sweep < 10; sweep++) {
#pragma unroll
        for (int p = 0; p < LT; p++)
#pragma unroll
            for (int q = p + 1; q < LT; q++) {
                float apq = Tt[p][q];
                if (fabsf(apq) < 1e-30f) continue;
                float tau = (Tt[q][q] - Tt[p][p]) / (2.0f * apq);
                float tt = ((tau >= 0.0f) ? 1.0f : -1.0f) / (fabsf(tau) + sqrtf(1.0f + tau * tau));
                float cc = rsqrtf(1.0f + tt * tt);
                float ss = tt * cc;
#pragma unroll
                for (int k = 0; k < LT; k++) {
                    float akp = Tt[k][p], akq = Tt[k][q];
                    Tt[k][p] = cc * akp - ss * akq;
                    Tt[k][q] = ss * akp + cc * akq;
                }
#pragma unroll
                for (int k = 0; k < LT; k++) {
                    float apk = Tt[p][k], aqk = Tt[q][k];
                    Tt[p][k] = cc * apk - ss * aqk;
                    Tt[q][k] = ss * apk + cc * aqk;
                }
#pragma unroll
                for (int k = 0; k < LT; k++) {
                    float ukp = U[k][p], ukq = U[k][q];
                    U[k][p] = cc * ukp - ss * ukq;
                    U[k][q] = ss * ukp + cc * ukq;
                }
            }
    }
    float R[LT][LT];
#pragma unroll
    for (int c = 0; c < LT; c++) {
        g_lambda[c] = Tt[c][c];
#pragma unroll
        for (int a = 0; a < LT; a++) {
            R[c][a] = U[a][c] * sv[a];
            g_R[c * LT + a] = R[c][a];
        }
    }
#pragma unroll
    for (int c = 0; c < LT; c++)
#pragma unroll
        for (int b = 0; b < LT; b++) {
            float m = 0.0f;
#pragma unroll
            for (int a = 0; a < LT; a++) m += R[c][a] * T[a][b];
            g_M[c * LT + b] = m;
        }
#pragma unroll
    for (int a = 0; a < LT; a++) {
#pragma unroll
        for (int b = 0; b < LT; b++) g_Tm[a * LT + b] = T[a][b];
        g_noise[a] = expf(log_noise[a]);
    }
}

// =====================================================================
// RBF kernels. mode 0: Cxx ; mode 1: Cx into B ; mode 2: A_c
// =====================================================================
__global__ void k_rbf(const float* __restrict__ X1, const float* __restrict__ X2,
                      const float* __restrict__ log_ls, int mode)
{
    __shared__ float xs1[16][8];
    __shared__ float xs2[16][8];
    int tid = threadIdx.x;
    int bx = blockIdx.x, by = blockIdx.y;
    if (tid < 128) {
        xs1[tid >> 3][tid & 7] = X1[(by * 16 + (tid >> 3)) * 8 + (tid & 7)];
    } else {
        int q = tid - 128;
        xs2[q >> 3][q & 7] = X2[(bx * 16 + (q >> 3)) * 8 + (q & 7)];
    }
    __syncthreads();
    int tx = tid & 15, ty = tid >> 4;
    float inv_ls2 = expf(-2.0f * log_ls[0]);
    float d2 = 0.0f;
#pragma unroll
    for (int d = 0; d < 8; d++) {
        float df = xs1[ty][d] - xs2[tx][d];
        d2 += df * df;
    }
    float kv = expf(-0.5f * d2 * inv_ls2);
    int i = by * 16 + ty, j = bx * 16 + tx;
    if (mode == 0) {
        g_Cxx[(size_t)i * NP + j] = kv;
    } else if (mode == 1) {
#pragma unroll
        for (int c = 0; c < LT; c++)
            g_B[(size_t)c * NP * NTOT + (size_t)i * NTOT + j] = kv;
    } else {
        float dg = (i == j) ? 1.0f : 0.0f;
#pragma unroll
        for (int c = 0; c < LT; c++)
            g_A[(size_t)c * NP * NP + (size_t)i * NP + j] = g_lambda[c] * kv + dg;
    }
}

// ytilde into column 1024 of each B_c + zero pad columns, coalesced.
__global__ void k_y(const float* __restrict__ Y)
{
    int idx = blockIdx.x * blockDim.x + threadIdx.x;   // < 4*1024*128
    if (idx >= LT * NP * 128) return;
    int p = idx & 127;
    int i = (idx >> 7) & 1023;
    int c = idx >> 17;
    float v = 0.0f;
    if (p == 0) {
#pragma unroll
        for (int a = 0; a < LT; a++) v += g_R[c * LT + a] * Y[i * LT + a];
    }
    g_B[(size_t)c * NP * NTOT + (size_t)i * NTOT + 1024 + p] = v;
}

// =====================================================================
// potf2 (kb=0 only): factor 64x64 diag block + produce L^{-1}
// =====================================================================
__global__ void k_potf2(int kb)
{
    int c = blockIdx.z;
    float* Ad = g_A + (size_t)c * NP * NP + (size_t)kb * 64 * NP + (size_t)kb * 64;
    float* Li = g_Linv + ((size_t)c * NKB + kb) * 64 * 64;
    __shared__ float s[64][65];
    __shared__ float vi[64][65];
    __shared__ float sdiag[64];
    int tid = threadIdx.x;
    int r = tid & 63, q = tid >> 6;
    for (int p = tid; p < 64 * 64; p += 256) {
        int rr = p >> 6, qq = p & 63;
        s[rr][qq] = Ad[(size_t)rr * NP + qq];
        vi[rr][qq] = (rr == qq) ? 1.0f : 0.0f;
    }
    __syncthreads();
#pragma unroll 1
    for (int j = 0; j < 64; j++) {
        float d = rsqrtf(s[j][j]);
        if (q == 0 && r > j)  s[r][j] *= d;
        if (q == 1 && r <= j) vi[j][r] *= d;
        if (q == 2 && r == j) sdiag[j] = s[j][j] * d;
        __syncthreads();
        if (r > j) {
            float sij = s[r][j];
            for (int t = j + 1 + q; t < 64; t += 4)
                s[r][t] -= sij * s[t][j];
            for (int t = q; t <= j; t += 4)
                vi[r][t] -= sij * vi[j][t];
        }
        __syncthreads();
    }
    for (int p = tid; p < 64 * 64; p += 256) {
        int rr = p >> 6, qq = p & 63;
        if (qq < rr) Ad[(size_t)rr * NP + qq] = s[rr][qq];
        else if (qq == rr) Ad[(size_t)rr * NP + qq] = sdiag[rr];
        Li[p] = vi[rr][qq];
    }
}

// =====================================================================
// combo1 (per kb): panel TRSM tiles + B diag-block solve, one launch
// =====================================================================
__global__ void k_combo1(int kb, int rem)
{
    int c = blockIdx.z;
    const float* Li = g_Linv + ((size_t)c * NKB + kb) * 4096;
    int panelTiles = rem >> 6;
    int bx = blockIdx.x;
    __shared__ float As[16][68];
    __shared__ float Bs[16][68];
    int tid = threadIdx.x, tx = tid & 15, ty = tid >> 4;
    unsigned long long accP[4][2];
#pragma unroll
    for (int i = 0; i < 4; i++) { accP[i][0] = 0ull; accP[i][1] = 0ull; }

    const float* Aop; const float* Bop; float* Cop;
    int lda, ldb, ldc; bool tb;
    if (bx < panelTiles) {
        float* panel = g_A + (size_t)c * NP * NP + (size_t)(kb + 1) * 64 * NP + (size_t)kb * 64;
        Aop = panel + (size_t)bx * 64 * NP; lda = NP;
        Bop = Li; ldb = 64; tb = true;
        Cop = (float*)Aop; ldc = NP;
    } else {
        int nb = bx - panelTiles;
        float* Bk = g_B + (size_t)c * NP * NTOT + (size_t)kb * 64 * NTOT;
        Aop = Li; lda = 64; tb = false;
        Bop = Bk + nb * 64; ldb = NTOT;
        Cop = (float*)Bop; ldc = NTOT;
    }
    for (int k0 = 0; k0 < 64; k0 += 16) {
        {
            int kl = tid & 15, ml = tid >> 4;
#pragma unroll
            for (int p = 0; p < 4; p++)
                As[kl][ml + p * 16] = Aop[(size_t)(ml + p * 16) * lda + (k0 + kl)];
        }
        if (!tb) {
            int nl = tid & 63, kl = tid >> 6;
#pragma unroll
            for (int p = 0; p < 4; p++)
                Bs[kl + p * 4][nl] = Bop[(size_t)(k0 + kl + p * 4) * ldb + nl];
        } else {
            int kl = tid & 15, nl = tid >> 4;
#pragma unroll
            for (int p = 0; p < 4; p++)
                Bs[kl][nl + p * 16] = Bop[(size_t)(nl + p * 16) * ldb + (k0 + kl)];
        }
        __syncthreads();
#pragma unroll
        for (int kk = 0; kk < 16; kk++) {
            float4 av = *(const float4*)&As[kk][ty * 4];
            float4 bv = *(const float4*)&Bs[kk][tx * 4];
            unsigned long long bp0 = f2pack(bv.x, bv.y);
            unsigned long long bp1 = f2pack(bv.z, bv.w);
            float a_[4] = {av.x, av.y, av.z, av.w};
#pragma unroll
            for (int i = 0; i < 4; i++) {
                unsigned long long ap = f2pack(a_[i], a_[i]);
                f2fma(accP[i][0], ap, bp0);
                f2fma(accP[i][1], ap, bp1);
            }
        }
        __syncthreads();
    }
#pragma unroll
    for (int i = 0; i < 4; i++) {
        float v0, v1, v2, v3;
        f2unpack(accP[i][0], v0, v1);
        f2unpack(accP[i][1], v2, v3);
        float* p = Cop + (size_t)(ty * 4 + i) * ldc + tx * 4;
        p[0] = v0; p[1] = v1; p[2] = v2; p[3] = v3;
    }
}

// =====================================================================
// combo2 (per kb) via split-bf16 HMMA:
//   jobA (bx < tilesA, lower): A_trail -= panel * panel^T
//   jobB:                      B[kb+1:] -= panel * B_kb
// CTA tile 128x128, K=64 (two 32-chunks). 8 warps (4m x 2n).
// CTA (0,0,jobA) factors the next 64x64 diag block (fused potf2).
// =====================================================================
constexpr int CRS = 40;  // smem row stride (bf16 elems)

__global__ __launch_bounds__(256)
void k_combo2_mma(int kb, int rem)
{
    __shared__ __align__(16) __nv_bfloat16 stage[4 * 128 * CRS];  // 40960 B
    __nv_bfloat16* sAh = stage;
    __nv_bfloat16* sAl = stage + 128 * CRS;
    __nv_bfloat16* sBh = stage + 2 * 128 * CRS;
    __nv_bfloat16* sBl = stage + 3 * 128 * CRS;
    float* pool = (float*)stage;     // aliased for fused potf2 (33792 B)

    int c = blockIdx.z;
    int tilesA = (rem + 127) >> 7;
    int bx = blockIdx.x, mb = blockIdx.y;
    bool jobA = bx < tilesA;
    if (jobA && bx > mb) return;
    const float* panel = g_A + (size_t)c * NP * NP + (size_t)(kb + 1) * 64 * NP + (size_t)kb * 64;
    const int M = rem;
    const float* Bk = g_B + (size_t)c * NP * NTOT + (size_t)kb * 64 * NTOT;
    float* Cop; int ldc; int N; int col0;
    if (jobA) {
        Cop = g_A + (size_t)c * NP * NP + (size_t)(kb + 1) * 64 * NP + (size_t)(kb + 1) * 64;
        ldc = NP; N = rem; col0 = bx * 128;
    } else {
        Cop = g_B + (size_t)c * NP * NTOT + (size_t)(kb + 1) * 64 * NTOT;
        ldc = NTOT; N = NTOT; col0 = (bx - tilesA) * 128;
    }
    const int row0 = mb * 128;
    int tid = threadIdx.x;
    int w = tid >> 5, lane = tid & 31;
    int wm = w & 3, wn = w >> 2;

    uint32_t bAh = smem_u32(sAh), bBh = smem_u32(sBh);
    uint32_t bAl = smem_u32(sAl), bBl = smem_u32(sBl);

    float acc[2][8][4];
#pragma unroll
    for (int i = 0; i < 2; i++)
#pragma unroll
        for (int j = 0; j < 8; j++)
#pragma unroll
            for (int v = 0; v < 4; v++) acc[i][j][v] = 0.0f;

    const uint32_t lmo = (uint32_t)((lane & 15) * CRS + ((lane >> 4) << 3)) * 2u;

#pragma unroll 1
    for (int k0 = 0; k0 < 64; k0 += 32) {
        // ---- stage A: panel rows (row0..row0+127) x k-chunk 32, split ----
#pragma unroll
        for (int it = 0; it < 4; it++) {
            int idx = tid + it * 256;          // 0..1023
            int r = idx >> 3, ch = idx & 7;    // row, float4 chunk (8 per row)
            int m = row0 + r; if (m >= M) m = M - 1;
            float4 v = *(const float4*)(panel + (size_t)m * NP + k0 + ch * 4);
            __nv_bfloat16 h0, h1, h2, h3, l0, l1, l2, l3;
            bfsplit(v.x, h0, l0); bfsplit(v.y, h1, l1);
            bfsplit(v.z, h2, l2); bfsplit(v.w, h3, l3);
            __nv_bfloat162* ph = (__nv_bfloat162*)(sAh + r * CRS + ch * 4);
            __nv_bfloat162* pl = (__nv_bfloat162*)(sAl + r * CRS + ch * 4);
            ph[0] = __halves2bfloat162(h0, h1); ph[1] = __halves2bfloat162(h2, h3);
            pl[0] = __halves2bfloat162(l0, l1); pl[1] = __halves2bfloat162(l2, l3);
        }
        // ---- stage B ----
        if (jobA) {
            // B = panel rows (col0..col0+127), same k-contiguous format
#pragma unroll
            for (int it = 0; it < 4; it++) {
                int idx = tid + it * 256;
                int r = idx >> 3, ch = idx & 7;
                int n = col0 + r; if (n >= N) n = N - 1;
                float4 v = *(const float4*)(panel + (size_t)n * NP + k0 + ch * 4);
                __nv_bfloat16 h0, h1, h2, h3, l0, l1, l2, l3;
                bfsplit(v.x, h0, l0); bfsplit(v.y, h1, l1);
                bfsplit(v.z, h2, l2); bfsplit(v.w, h3, l3);
                __nv_bfloat162* ph = (__nv_bfloat162*)(sBh + r * CRS + ch * 4);
                __nv_bfloat162* pl = (__nv_bfloat162*)(sBl + r * CRS + ch * 4);
                ph[0] = __halves2bfloat162(h0, h1); ph[1] = __halves2bfloat162(h2, h3);
                pl[0] = __halves2bfloat162(l0, l1); pl[1] = __halves2bfloat162(l2, l3);
            }
        } else {
            // B_kb[k][n]: transpose to smem [n][k] during split
            int n4 = (tid & 31) * 4;
            int kk = tid >> 5;                 // 0..7
#pragma unroll
            for (int p = 0; p < 4; p++) {
                int k = kk + p * 8;            // local k 0..31
                float4 v = *(const float4*)(Bk + (size_t)(k0 + k) * NTOT + col0 + n4);
                __nv_bfloat16 h, l;
                bfsplit(v.x, h, l); sBh[(n4 + 0) * CRS + k] = h; sBl[(n4 + 0) * CRS + k] = l;
                bfsplit(v.y, h, l); sBh[(n4 + 1) * CRS + k] = h; sBl[(n4 + 1) * CRS + k] = l;
                bfsplit(v.z, h, l); sBh[(n4 + 2) * CRS + k] = h; sBl[(n4 + 2) * CRS + k] = l;
                bfsplit(v.w, h, l); sBh[(n4 + 3) * CRS + k] = h; sBl[(n4 + 3) * CRS + k] = l;
            }
        }
        __syncthreads();
        // ---- compute: identical fragment pattern to validated hgemm ----
#pragma unroll
        for (int ks = 0; ks < 32; ks += 16) {
            uint32_t Ah[2][4], Al[2][4];
#pragma unroll
            for (int mt = 0; mt < 2; mt++) {
                uint32_t off = (uint32_t)((wm * 32 + mt * 16) * CRS + ks) * 2u + lmo;
                ldmx4(Ah[mt], bAh + off);
                ldmx4(Al[mt], bAl + off);
            }
#pragma unroll
            for (int np = 0; np < 4; np++) {
                uint32_t Bh[4], Bl[4];
                uint32_t off = (uint32_t)((wn * 64 + np * 16) * CRS + ks) * 2u + lmo;
                ldmx4(Bh, bBh + off);
                ldmx4(Bl, bBl + off);
#pragma unroll
                for (int sub = 0; sub < 2; sub++) {
                    int nt = np * 2 + sub;
#pragma unroll
                    for (int mt = 0; mt < 2; mt++) {
                        mma16816(acc[mt][nt], Ah[mt], Bh[sub], Bh[sub + 2]);
                        mma16816(acc[mt][nt], Ah[mt], Bl[sub], Bl[sub + 2]);
                        mma16816(acc[mt][nt], Al[mt], Bh[sub], Bh[sub + 2]);
                    }
                }
            }
        }
        __syncthreads();
    }

    // ---- epilogue: C -= acc (RMW); capture diag block for fused potf2 ----
    bool fuse = jobA && bx == 0 && mb == 0 && (kb + 1 < NKB);
    int gr = lane >> 2, gc = (lane & 3) << 1;
#pragma unroll
    for (int mt = 0; mt < 2; mt++) {
#pragma unroll
        for (int half = 0; half < 2; half++) {
            int m = row0 + wm * 32 + mt * 16 + gr + half * 8;
            if (m >= M) continue;
#pragma unroll
            for (int nt = 0; nt < 8; nt++) {
                int n = col0 + wn * 64 + nt * 8 + gc;
                if (n >= N) continue;
                float a0 = acc[mt][nt][half * 2 + 0];
                float a1 = acc[mt][nt][half * 2 + 1];
                float* p = Cop + (size_t)m * ldc + n;
                float2 o = *(float2*)p;
                o.x -= a0; o.y -= a1;
                *(float2*)p = o;
                if (fuse && m < 64 && n < 64) {
                    pool[m * 65 + n + 0] = o.x;
                    pool[m * 65 + n + 1] = o.y;
                }
            }
        }
    }

    if (fuse) {
        // ---- fused potf2(kb+1): factor + invert 64x64 from pool ----
        float* s  = pool;          // [64][65]
        float* vi = pool + 4224;   // [64][65]
        float* sd = pool + 8384;   // [64]
        int r = tid & 63, q = tid >> 6;
        for (int p = tid; p < 64 * 64; p += 256)
            vi[(p >> 6) * 65 + (p & 63)] = ((p >> 6) == (p & 63)) ? 1.0f : 0.0f;
        __syncthreads();
#pragma unroll 1
        for (int j = 0; j < 64; j++) {
            float d = rsqrtf(s[j * 65 + j]);
            if (q == 0 && r > j)  s[r * 65 + j] *= d;
            if (q == 1 && r <= j) vi[j * 65 + r] *= d;
            if (q == 2 && r == j) sd[j] = s[j * 65 + j] * d;
            __syncthreads();
            if (r > j) {
                float sij = s[r * 65 + j];
                for (int t = j + 1 + q; t < 64; t += 4)
                    s[r * 65 + t] -= sij * s[t * 65 + j];
                for (int t = q; t <= j; t += 4)
                    vi[r * 65 + t] -= sij * vi[j * 65 + t];
            }
            __syncthreads();
        }
        int kbn = kb + 1;
        float* Ad = g_A + (size_t)c * NP * NP + (size_t)kbn * 64 * NP + (size_t)kbn * 64;
        float* Li = g_Linv + ((size_t)c * NKB + kbn) * 4096;
        for (int p = tid; p < 64 * 64; p += 256) {
            int rr = p >> 6, qq = p & 63;
            if (qq < rr) Ad[(size_t)rr * NP + qq] = s[rr * 65 + qq];
            else if (qq == rr) Ad[(size_t)rr * NP + qq] = sd[rr];
            Li[p] = vi[rr * 65 + qq];
        }
    }
}

// =====================================================================
// Q split: Q = P^T (K-major), bf16 hi + bf16 residual lo
// =====================================================================
__global__ void k_qsplit()
{
    __shared__ float s[32][33];
    int c = blockIdx.z;
    int k0 = blockIdx.x * 32, j0 = blockIdx.y * 32;
    const float* P = g_B + (size_t)c * NP * NTOT;
    int x = threadIdx.x, y = threadIdx.y;
    for (int yy = y; yy < 32; yy += 8)
        s[yy][x] = P[(size_t)(k0 + yy) * NTOT + j0 + x];
    __syncthreads();
    __nv_bfloat16* Qh = g_Qh + (size_t)c * NTOT * NP;
    __nv_bfloat16* Ql = g_Ql + (size_t)c * NTOT * NP;
    for (int yy = y; yy < 32; yy += 8) {
        float v = s[x][yy];
        __nv_bfloat16 h = __float2bfloat16(v);
        float l = v - __bfloat162float(h);
        Qh[(size_t)(j0 + yy) * NP + k0 + x] = h;
        Ql[(size_t)(j0 + yy) * NP + k0 + x] = __float2bfloat16(l);
    }
}

// =====================================================================
// H GEMM via mma.sync bf16 split: H = Qh Qh^T + Qh Ql^T + Ql Qh^T
// =====================================================================
constexpr int QRS = 40;

__global__ __launch_bounds__(256)
void k_hgemm_mma()
{
    int nb = blockIdx.x, mb = blockIdx.y;
    if (nb > mb && nb != (int)gridDim.x - 1) return;
    int c = blockIdx.z;
    const __nv_bfloat16* Qh = g_Qh + (size_t)c * NTOT * NP;
    const __nv_bfloat16* Ql = g_Ql + (size_t)c * NTOT * NP;
    const int row0 = mb * 128, col0 = nb * 128;

    __shared__ __align__(16) __nv_bfloat16 sAh[128 * QRS];
    __shared__ __align__(16) __nv_bfloat16 sBh[128 * QRS];
    __shared__ __align__(16) __nv_bfloat16 sAl[128 * QRS];
    __shared__ __align__(16) __nv_bfloat16 sBl[128 * QRS];

    int tid = threadIdx.x;
    int w = tid >> 5, lane = tid & 31;
    int wm = w & 3, wn = w >> 2;

    uint32_t bAh = smem_u32(sAh), bBh = smem_u32(sBh);
    uint32_t bAl = smem_u32(sAl), bBl = smem_u32(sBl);

    float acc[2][8][4];
#pragma unroll
    for (int i = 0; i < 2; i++)
#pragma unroll
        for (int j = 0; j < 8; j++)
#pragma unroll
            for (int v = 0; v < 4; v++) acc[i][j][v] = 0.0f;

    const uint32_t lmo = (uint32_t)((lane & 15) * QRS + ((lane >> 4) << 3)) * 2u;

#pragma unroll 1
    for (int k0 = 0; k0 < NP; k0 += 32) {
#pragma unroll
        for (int it = 0; it < 2; it++) {
            int idx = tid + it * 256;
            int r = idx >> 2, ch = idx & 3;
            const int4* gah = (const int4*)(Qh + (size_t)(row0 + r) * NP + k0) + ch;
            const int4* gbh = (const int4*)(Qh + (size_t)(col0 + r) * NP + k0) + ch;
            const int4* gal = (const int4*)(Ql + (size_t)(row0 + r) * NP + k0) + ch;
            const int4* gbl = (const int4*)(Ql + (size_t)(col0 + r) * NP + k0) + ch;
            *(int4*)(sAh + r * QRS + ch * 8) = *gah;
            *(int4*)(sBh + r * QRS + ch * 8) = *gbh;
            *(int4*)(sAl + r * QRS + ch * 8) = *gal;
            *(int4*)(sBl + r * QRS + ch * 8) = *gbl;
        }
        __syncthreads();
#pragma unroll
        for (int ks = 0; ks < 32; ks += 16) {
            uint32_t Ah[2][4], Al[2][4];
#pragma unroll
            for (int mt = 0; mt < 2; mt++) {
                uint32_t off = (uint32_t)((wm * 32 + mt * 16) * QRS + ks) * 2u + lmo;
                ldmx4(Ah[mt], bAh + off);
                ldmx4(Al[mt], bAl + off);
            }
#pragma unroll
            for (int np = 0; np < 4; np++) {
                uint32_t Bh[4], Bl[4];
                uint32_t off = (uint32_t)((wn * 64 + np * 16) * QRS + ks) * 2u + lmo;
                ldmx4(Bh, bBh + off);
                ldmx4(Bl, bBl + off);
#pragma unroll
                for (int sub = 0; sub < 2; sub++) {
                    int nt = np * 2 + sub;
#pragma unroll
                    for (int mt = 0; mt < 2; mt++) {
                        mma16816(acc[mt][nt], Ah[mt], Bh[sub], Bh[sub + 2]);
                        mma16816(acc[mt][nt], Ah[mt], Bl[sub], Bl[sub + 2]);
                        mma16816(acc[mt][nt], Al[mt], Bh[sub], Bh[sub + 2]);
                    }
                }
            }
        }
        __syncthreads();
    }

    float* H = g_H + (size_t)c * NP * NTOT;
    int gr = lane >> 2, gc = (lane & 3) << 1;
#pragma unroll
    for (int mt = 0; mt < 2; mt++) {
        int m = row0 + wm * 32 + mt * 16 + gr;
#pragma unroll
        for (int nt = 0; nt < 8; nt++) {
            int n = col0 + wn * 64 + nt * 8 + gc;
            *(float2*)(H + (size_t)m * NTOT + n)       = make_float2(acc[mt][nt][0], acc[mt][nt][1]);
            *(float2*)(H + (size_t)(m + 8) * NTOT + n) = make_float2(acc[mt][nt][2], acc[mt][nt][3]);
        }
    }
}

// =====================================================================
// Symmetrize H: copy lower triangle -> upper (cols < 1024 only)
// =====================================================================
__global__ void k_symH()
{
    int tc = blockIdx.x, tr = blockIdx.y;
    if (tc < tr) return;
    int c = blockIdx.z;
    float* H = g_H + (size_t)c * NP * NTOT;
    __shared__ float s[32][33];
    int x = threadIdx.x, y0 = threadIdx.y;
    for (int yy = y0; yy < 32; yy += 8)
        s[yy][x] = H[(size_t)(tc * 32 + yy) * NTOT + tr * 32 + x];
    __syncthreads();
    for (int yy = y0; yy < 32; yy += 8) {
        int i = tr * 32 + yy, j = tc * 32 + x;
        if (j > i) H[(size_t)i * NTOT + j] = s[x][yy];
    }
}

// =====================================================================
// Final outputs
// =====================================================================
__global__ void k_fmean(float* __restrict__ out)
{
    int idx = blockIdx.x * blockDim.x + threadIdx.x;
    if (idx >= 4096) return;
    int b = idx >> 10, j = idx & 1023;
    float v = 0.0f;
#pragma unroll
    for (int c = 0; c < LT; c++)
        v += g_M[c * LT + b] * g_H[(size_t)c * NP * NTOT + (size_t)j * NTOT + 1024];
    out[OFF_FMEAN + idx] = v;
    out[OFF_OUT4 + (size_t)j * LT + b] = v;
}

__global__ void k_output(float* __restrict__ out)
{
    size_t t = (size_t)blockIdx.x * blockDim.x + threadIdx.x;
    if (t >= (size_t)4096 * 1024) return;
    int g = (int)(t & 1023);
    size_t ig = t >> 10;
    int a = (int)(ig >> 10);
    int i = (int)(ig & 1023);
    int b = g >> 8;
    int j0 = (g & 255) << 2;
    float4 cxx = *(const float4*)&g_Cxx[(size_t)i * NP + j0];
    float Tab = g_Tm[a * LT + b];
    float4 acc;
    acc.x = Tab * cxx.x;
    acc.y = Tab * cxx.y;
    acc.z = Tab * cxx.z;
    acc.w = Tab * cxx.w;
#pragma unroll
    for (int c = 0; c < LT; c++) {
        float mm = g_M[c * LT + a] * g_M[c * LT + b];
        float4 h = *(const float4*)&g_H[(size_t)c * NP * NTOT + (size_t)i * NTOT + j0];
        acc.x -= mm * h.x;
        acc.y -= mm * h.y;
        acc.z -= mm * h.z;
        acc.w -= mm * h.w;
    }
    size_t col0 = (size_t)b * 1024 + j0;
    *(float4*)&out[OFF_FVAR + ig * 4096 + col0] = acc;
    float4 nz = make_float4(0.f, 0.f, 0.f, 0.f);
    if (ig >= col0 && ig < col0 + 4) {
        float nv = g_noise[a];
        int jj = (int)(ig - col0);
        if (jj == 0) nz.x = nv;
        else if (jj == 1) nz.y = nv;
        else if (jj == 2) nz.z = nv;
        else nz.w = nv;
    }
    *(float4*)&out[OFF_NOISE + ig * 4096 + col0] = nz;
}

// =====================================================================
// Host side
// =====================================================================
extern "C" void kernel_launch(void* const* d_in, const int* in_sizes, int n_in,
                              void* d_out, int out_size)
{
    const float* X        = (const float*)d_in[0];
    const float* test_X   = (const float*)d_in[1];
    const float* Y        = (const float*)d_in[2];
    const float* lnoise   = (const float*)d_in[3];
    const float* cfac     = (const float*)d_in[4];
    const float* lvar     = (const float*)d_in[5];
    const float* lls      = (const float*)d_in[6];
    int rank = in_sizes[4] / LT;
    float* out = (float*)d_out;

    k_setup<<<1, 32>>>(cfac, lvar, lnoise, rank);
    dim3 rg(64, 64);
    k_rbf<<<rg, 256>>>(X, X, lls, 2);           // A_c = lambda_c*C + I
    k_rbf<<<rg, 256>>>(X, test_X, lls, 1);      // Cx into B_c
    k_rbf<<<rg, 256>>>(test_X, test_X, lls, 0); // Cxx
    k_y<<<(LT * NP * 128 + 255) / 256, 256>>>(Y);

    // ---- batched blocked Cholesky fused with forward solve ----
    k_potf2<<<dim3(1, 1, LT), 256>>>(0);
    for (int kb = 0; kb < NKB; kb++) {
        int rem = NP - 64 * (kb + 1);
        k_combo1<<<dim3((rem >> 6) + (NTOT >> 6), 1, LT), 256>>>(kb, rem);
        if (rem > 0) {
            int tilesA = (rem + 127) >> 7;
            k_combo2_mma<<<dim3(tilesA + (NTOT >> 7), tilesA, LT), 256>>>(kb, rem);
        }
    }

    // ---- Q = P^T in split bf16, then H = Q Q^T on tensor cores ----
    k_qsplit<<<dim3(32, 36, LT), dim3(32, 8)>>>();
    k_hgemm_mma<<<dim3(NTOT / 128, NP / 128, LT), 256>>>();
    k_symH<<<dim3(32, 32, LT), dim3(32, 8)>>>();

    // ---- outputs ----
    k_fmean<<<16, 256>>>(out);
    k_output<<<16384, 256>>>(out);
}